// round 8
// baseline (speedup 1.0000x reference)
#include <cuda_runtime.h>

// SWAttention AV — block-per-16-row-tile, cp.async, 128 threads (4 warps, zero idle).
// B=8, H=8, N=3136, D=32, K2=9. smem ~22.3KB -> 10 CTAs/SM.
// Phase 1: attn[n,k] = q[n,:]·lt[:,k] + bias + local   (t -> (n=t>>3, k=t&7); k==0 lanes also k=8)
// Phase 2: out[n,d]  = sum_k attn[n,k]*v[n,d,k]        (4 warps x 4 rows, 128-bit LSU ops)

#define HH 8
#define NN 3136
#define NROWS (8 * HH * NN)       // 200704
#define TILE 16
#define NBLOCKS (NROWS / TILE)    // 12544
#define NTHREADS 128

__device__ __forceinline__ unsigned smem_u32(const void* p) {
    return (unsigned)__cvta_generic_to_shared(p);
}
__device__ __forceinline__ void cp16(unsigned dst, const void* src) {
    asm volatile("cp.async.cg.shared.global [%0], [%1], 16;" :: "r"(dst), "l"(src));
}
__device__ __forceinline__ void cp_commit() {
    asm volatile("cp.async.commit_group;");
}

__global__ __launch_bounds__(NTHREADS, 10)
void swattn_kernel(const float* __restrict__ q,
                   const float* __restrict__ attn_local,
                   const float* __restrict__ v,
                   const float* __restrict__ lt,
                   const float* __restrict__ bias,
                   float* __restrict__ out) {
    __shared__ float sq[TILE * 36];    //  2304 B, padded rows (conflict-free f4)
    __shared__ float sv[TILE * 288];   // 18432 B, flat contiguous tile
    __shared__ float sltT[9 * 36];     //  1296 B, lt transposed [k][d], padded
    __shared__ float sa[TILE * 12];    //   768 B, attn tile

    const int t    = threadIdx.x;
    const int w    = t >> 5;
    const int lane = t & 31;

    const size_t R0  = (size_t)blockIdx.x * TILE;
    const int    hn0 = (int)(R0 % (HH * NN));
    const int    h   = hn0 / NN;

    // ---- Group 0: q tile via cp.async (128 x 16B, one per thread, padded dst) ----
    cp16(smem_u32(sq + (t >> 3) * 36 + (t & 7) * 4), q + R0 * 32 + t * 4);
    cp_commit();

    // ---- Group 1: v tile via cp.async (1152 x 16B = exactly 9 per thread) ----
    {
        const float*   vg = v + R0 * 288;
        const unsigned sd = smem_u32(sv);
        #pragma unroll
        for (int j = 0; j < 9; j++) {
            const int c = t + NTHREADS * j;
            cp16(sd + c * 16, vg + c * 4);
        }
    }
    cp_commit();

    // ---- Stage lt transposed: sltT[k][d] = lt[h][d][k] (288 elems, strided) ----
    #pragma unroll
    for (int i = t; i < 288; i += NTHREADS) {
        const int d = i / 9, k = i - 9 * d;
        sltT[k * 36 + d] = lt[h * 288 + i];
    }

    // ---- bias + local into registers (overlaps the waits) ----
    const int n = t >> 3;
    const int k = t & 7;
    const int rk = n * 9 + k;
    float bl  = bias[(size_t)hn0 * 9 + rk] + __ldcs(attn_local + R0 * 9 + rk);
    float bl8 = 0.f;
    if (k == 0)
        bl8 = bias[(size_t)hn0 * 9 + n * 9 + 8] + __ldcs(attn_local + R0 * 9 + n * 9 + 8);

    asm volatile("cp.async.wait_group 1;");   // q done; v still streaming
    __syncthreads();

    // ---- Phase 1: attn. Thread (n, k); k==0 lanes also compute k=8 ----
    {
        const float4* q4 = reinterpret_cast<const float4*>(sq + n * 36);
        const float4* l4 = reinterpret_cast<const float4*>(sltT + k * 36);
        const float4* l8 = reinterpret_cast<const float4*>(sltT + 8 * 36);
        float acc = bl, acc8 = bl8;
        #pragma unroll
        for (int i = 0; i < 8; i++) {
            const float4 qa = q4[i], lb = l4[i];
            acc = fmaf(qa.x, lb.x, acc);
            acc = fmaf(qa.y, lb.y, acc);
            acc = fmaf(qa.z, lb.z, acc);
            acc = fmaf(qa.w, lb.w, acc);
            if (k == 0) {
                const float4 lc = l8[i];
                acc8 = fmaf(qa.x, lc.x, acc8);
                acc8 = fmaf(qa.y, lc.y, acc8);
                acc8 = fmaf(qa.z, lc.z, acc8);
                acc8 = fmaf(qa.w, lc.w, acc8);
            }
        }
        sa[n * 12 + k] = acc;
        if (k == 0) sa[n * 12 + 8] = acc8;
    }

    asm volatile("cp.async.wait_group 0;");   // v done
    __syncthreads();

    // ---- Phase 2: AV. Warp w -> rows 4w..4w+3. Lane: row = lane>>3, d-group = lane&7 ----
    {
        const int row = (w << 2) + (lane >> 3);   // tile-local row 0..15
        const int g7  = lane & 7;

        const float* sar = sa + row * 12;
        const float4 A0 = reinterpret_cast<const float4*>(sar)[0];
        const float4 A1 = reinterpret_cast<const float4*>(sar)[1];
        const float a[9] = {A0.x, A0.y, A0.z, A0.w, A1.x, A1.y, A1.z, A1.w, sar[8]};

        // Lane's 36 contiguous floats = v[row][4*g7 .. 4*g7+3][0..8]; static (d,k) decode.
        const float4* wv4 = reinterpret_cast<const float4*>(sv + row * 288 + g7 * 36);
        float acc[4] = {0.f, 0.f, 0.f, 0.f};
        #pragma unroll
        for (int i = 0; i < 9; i++) {
            const float4 wv = wv4[i];
            acc[(4 * i + 0) / 9] = fmaf(a[(4 * i + 0) % 9], wv.x, acc[(4 * i + 0) / 9]);
            acc[(4 * i + 1) / 9] = fmaf(a[(4 * i + 1) % 9], wv.y, acc[(4 * i + 1) / 9]);
            acc[(4 * i + 2) / 9] = fmaf(a[(4 * i + 2) % 9], wv.z, acc[(4 * i + 2) / 9]);
            acc[(4 * i + 3) / 9] = fmaf(a[(4 * i + 3) % 9], wv.w, acc[(4 * i + 3) / 9]);
        }

        const float4 o = make_float4(acc[0], acc[1], acc[2], acc[3]);
        __stcs(reinterpret_cast<float4*>(out + (R0 + row) * 32 + 4 * g7), o);
    }
}

extern "C" void kernel_launch(void* const* d_in, const int* in_sizes, int n_in,
                              void* d_out, int out_size) {
    const float* q          = (const float*)d_in[0];  // [B,H,N,D]
    const float* attn_local = (const float*)d_in[1];  // [B,H,N,K2]
    const float* v_local    = (const float*)d_in[2];  // [B,H,N,D,K2]
    const float* lt         = (const float*)d_in[3];  // [H,D,K2]
    const float* bias       = (const float*)d_in[4];  // [H,N,K2]
    float* out = (float*)d_out;                       // [B,H,N,D]

    swattn_kernel<<<NBLOCKS, NTHREADS>>>(q, attn_local, v_local, lt, bias, out);
}